// round 4
// baseline (speedup 1.0000x reference)
#include <cuda_runtime.h>
#include <math.h>

#define N_NODES 50000
#define N_EDGES 600000
#define IN_DIM  512
#define HIDDEN  128
#define OUT_DIM 64
#define EPS     0.1f

// ---------------- scratch (device globals; no allocation allowed) ----------------
__device__ float g_h0[(size_t)N_NODES * HIDDEN];   // raw (post-relu GEMM1 output)
__device__ float g_hA[(size_t)N_NODES * HIDDEN];
__device__ float g_hB[(size_t)N_NODES * HIDDEN];
__device__ float g_al[N_NODES];
__device__ float g_ar[N_NODES];
__device__ float g_dinv[N_NODES];
__device__ int   g_deg[N_NODES];
__device__ int   g_ptr[N_NODES + 1];
__device__ int   g_fill[N_NODES];
__device__ int   g_csr_src[N_EDGES];

// ---------------- CSR build ----------------
__global__ void zero_deg_kernel() {
    int i = blockIdx.x * blockDim.x + threadIdx.x;
    if (i < N_NODES) g_deg[i] = 0;
}

__global__ void hist_kernel(const int* __restrict__ dst) {
    int e = blockIdx.x * blockDim.x + threadIdx.x;
    if (e < N_EDGES) atomicAdd(&g_deg[dst[e]], 1);
}

// single-block exclusive scan over 50000 degrees; also fills g_fill and g_dinv
__global__ void scan_kernel() {
    __shared__ int partial[1024];
    const int t = threadIdx.x;
    const int CH = (N_NODES + 1023) / 1024;   // 49
    int beg = t * CH;
    int sum = 0;
    for (int i = 0; i < CH; i++) {
        int idx = beg + i;
        if (idx < N_NODES) sum += g_deg[idx];
    }
    partial[t] = sum;
    __syncthreads();
    if (t == 0) {
        int run = 0;
        for (int i = 0; i < 1024; i++) { int v = partial[i]; partial[i] = run; run += v; }
    }
    __syncthreads();
    int run = partial[t];
    for (int i = 0; i < CH; i++) {
        int idx = beg + i;
        if (idx < N_NODES) {
            g_ptr[idx]  = run;
            g_fill[idx] = run;
            int d = g_deg[idx];
            g_dinv[idx] = (d > 0) ? rsqrtf((float)d) : 0.0f;
            run += d;
        }
    }
    if (t == 0) g_ptr[N_NODES] = N_EDGES;
}

__global__ void scatter_kernel(const int* __restrict__ src, const int* __restrict__ dst) {
    int e = blockIdx.x * blockDim.x + threadIdx.x;
    if (e < N_EDGES) {
        int p = atomicAdd(&g_fill[dst[e]], 1);
        g_csr_src[p] = src[e];
    }
}

// ---------------- GEMM1: h = relu(x @ w1^T + b1)   [50000,512]x[128,512] ----------------
// classic smem-tiled SGEMM, BM=128, BN=128, BK=32, 256 threads, 8x8 per thread (2x2 of 4x4)
__global__ __launch_bounds__(256) void gemm1_relu_kernel(
    const float* __restrict__ x, const float* __restrict__ w,
    const float* __restrict__ bias, float* __restrict__ out)
{
    __shared__ float As[32][132];   // [k][m], padded
    __shared__ float Bs[32][132];   // [k][n]
    const int block_m = blockIdx.x * 128;
    const int tid = threadIdx.x;
    const int tx = tid & 15;        // col group
    const int ty = tid >> 4;        // row group

    float acc[8][8];
    #pragma unroll
    for (int i = 0; i < 8; i++)
        #pragma unroll
        for (int j = 0; j < 8; j++) acc[i][j] = 0.0f;

    for (int k0 = 0; k0 < IN_DIM; k0 += 32) {
        #pragma unroll
        for (int i = 0; i < 4; i++) {
            int f4  = tid + 256 * i;        // 0..1023
            int row = f4 >> 3;              // 0..127
            int col = (f4 & 7) * 4;         // 0..28
            int gm = block_m + row;
            float4 v = make_float4(0.f, 0.f, 0.f, 0.f);
            if (gm < N_NODES)
                v = *(const float4*)(x + (size_t)gm * IN_DIM + k0 + col);
            As[col + 0][row] = v.x; As[col + 1][row] = v.y;
            As[col + 2][row] = v.z; As[col + 3][row] = v.w;
            float4 u = *(const float4*)(w + (size_t)row * IN_DIM + k0 + col);
            Bs[col + 0][row] = u.x; Bs[col + 1][row] = u.y;
            Bs[col + 2][row] = u.z; Bs[col + 3][row] = u.w;
        }
        __syncthreads();
        #pragma unroll
        for (int k = 0; k < 32; k++) {
            float4 a0 = *(const float4*)&As[k][ty * 4];
            float4 a1 = *(const float4*)&As[k][64 + ty * 4];
            float4 b0 = *(const float4*)&Bs[k][tx * 4];
            float4 b1 = *(const float4*)&Bs[k][64 + tx * 4];
            float a[8] = {a0.x, a0.y, a0.z, a0.w, a1.x, a1.y, a1.z, a1.w};
            float b[8] = {b0.x, b0.y, b0.z, b0.w, b1.x, b1.y, b1.z, b1.w};
            #pragma unroll
            for (int i = 0; i < 8; i++)
                #pragma unroll
                for (int j = 0; j < 8; j++)
                    acc[i][j] = fmaf(a[i], b[j], acc[i][j]);
        }
        __syncthreads();
    }

    #pragma unroll
    for (int i = 0; i < 8; i++) {
        int rr = (i < 4) ? (ty * 4 + i) : (64 + ty * 4 + (i - 4));
        int gm = block_m + rr;
        if (gm >= N_NODES) continue;
        #pragma unroll
        for (int j = 0; j < 8; j++) {
            int cc = (j < 4) ? (tx * 4 + j) : (64 + tx * 4 + (j - 4));
            float v = acc[i][j] + bias[cc];
            out[(size_t)gm * HIDDEN + cc] = fmaxf(v, 0.0f);
        }
    }
}

// ---------------- per-layer: al/ar = h . att ----------------
__global__ void alar_kernel(const float* __restrict__ h,
                            const float* __restrict__ attl,
                            const float* __restrict__ attr)
{
    int gw   = (blockIdx.x * blockDim.x + threadIdx.x) >> 5;
    int lane = threadIdx.x & 31;
    if (gw >= N_NODES) return;
    float4 hv = *((const float4*)(h + (size_t)gw * HIDDEN) + lane);
    float4 lv = ((const float4*)attl)[lane];
    float4 rv = ((const float4*)attr)[lane];
    float sl = hv.x * lv.x + hv.y * lv.y + hv.z * lv.z + hv.w * lv.w;
    float sr = hv.x * rv.x + hv.y * rv.y + hv.z * rv.z + hv.w * rv.w;
    #pragma unroll
    for (int o = 16; o; o >>= 1) {
        sl += __shfl_xor_sync(0xffffffffu, sl, o);
        sr += __shfl_xor_sync(0xffffffffu, sr, o);
    }
    if (lane == 0) { g_al[gw] = sl; g_ar[gw] = sr; }
}

// ---------------- per-layer: aggregation (warp per node, CSR, no atomics) ----------------
__global__ void agg_kernel(const float* __restrict__ hcur,
                           const float* __restrict__ raw,
                           float* __restrict__ hnext)
{
    int node = (blockIdx.x * blockDim.x + threadIdx.x) >> 5;
    int lane = threadIdx.x & 31;
    if (node >= N_NODES) return;

    const int beg = g_ptr[node];
    const int end = g_ptr[node + 1];
    const float di  = g_dinv[node];
    const float ari = g_ar[node];

    float4 rv = *((const float4*)(raw + (size_t)node * HIDDEN) + lane);
    float4 acc = make_float4(EPS * rv.x, EPS * rv.y, EPS * rv.z, EPS * rv.w);

    for (int j = beg; j < end; j++) {
        int s = __ldg(&g_csr_src[j]);
        float wgt = tanhf(__ldg(&g_al[s]) + ari) * (__ldg(&g_dinv[s]) * di);
        float4 hs = __ldg((const float4*)(hcur + (size_t)s * HIDDEN) + lane);
        acc.x = fmaf(wgt, hs.x, acc.x);
        acc.y = fmaf(wgt, hs.y, acc.y);
        acc.z = fmaf(wgt, hs.z, acc.z);
        acc.w = fmaf(wgt, hs.w, acc.w);
    }
    *((float4*)(hnext + (size_t)node * HIDDEN) + lane) = acc;
}

// ---------------- GEMM2: emb = h @ w2^T + b2   [50000,128]x[64,128] ----------------
// BM=128, BN=64, BK=32, 256 threads, 8x4 per thread
__global__ __launch_bounds__(256) void gemm2_kernel(
    const float* __restrict__ h, const float* __restrict__ w2,
    const float* __restrict__ b2, float* __restrict__ emb)
{
    __shared__ float As[32][132];
    __shared__ float Bs[32][68];
    const int block_m = blockIdx.x * 128;
    const int tid = threadIdx.x;
    const int tx = tid & 15;
    const int ty = tid >> 4;

    float acc[8][4];
    #pragma unroll
    for (int i = 0; i < 8; i++)
        #pragma unroll
        for (int j = 0; j < 4; j++) acc[i][j] = 0.0f;

    for (int k0 = 0; k0 < HIDDEN; k0 += 32) {
        #pragma unroll
        for (int i = 0; i < 4; i++) {
            int f4  = tid + 256 * i;
            int row = f4 >> 3;
            int col = (f4 & 7) * 4;
            int gm = block_m + row;
            float4 v = make_float4(0.f, 0.f, 0.f, 0.f);
            if (gm < N_NODES)
                v = *(const float4*)(h + (size_t)gm * HIDDEN + k0 + col);
            As[col + 0][row] = v.x; As[col + 1][row] = v.y;
            As[col + 2][row] = v.z; As[col + 3][row] = v.w;
        }
        #pragma unroll
        for (int i = 0; i < 2; i++) {
            int f4  = tid + 256 * i;        // 0..511
            int row = f4 >> 3;              // 0..63
            int col = (f4 & 7) * 4;
            float4 u = *(const float4*)(w2 + (size_t)row * HIDDEN + k0 + col);
            Bs[col + 0][row] = u.x; Bs[col + 1][row] = u.y;
            Bs[col + 2][row] = u.z; Bs[col + 3][row] = u.w;
        }
        __syncthreads();
        #pragma unroll
        for (int k = 0; k < 32; k++) {
            float4 a0 = *(const float4*)&As[k][ty * 4];
            float4 a1 = *(const float4*)&As[k][64 + ty * 4];
            float4 b0 = *(const float4*)&Bs[k][tx * 4];
            float a[8] = {a0.x, a0.y, a0.z, a0.w, a1.x, a1.y, a1.z, a1.w};
            float b[4] = {b0.x, b0.y, b0.z, b0.w};
            #pragma unroll
            for (int i = 0; i < 8; i++)
                #pragma unroll
                for (int j = 0; j < 4; j++)
                    acc[i][j] = fmaf(a[i], b[j], acc[i][j]);
        }
        __syncthreads();
    }

    #pragma unroll
    for (int i = 0; i < 8; i++) {
        int rr = (i < 4) ? (ty * 4 + i) : (64 + ty * 4 + (i - 4));
        int gm = block_m + rr;
        if (gm >= N_NODES) continue;
        #pragma unroll
        for (int j = 0; j < 4; j++) {
            int cc = tx * 4 + j;
            emb[(size_t)gm * OUT_DIM + cc] = acc[i][j] + b2[cc];
        }
    }
}

// ---------------- log_softmax over 64 cols (warp per node) ----------------
__global__ void logsoftmax_kernel(const float* __restrict__ emb, float* __restrict__ out)
{
    int node = (blockIdx.x * blockDim.x + threadIdx.x) >> 5;
    int lane = threadIdx.x & 31;
    if (node >= N_NODES) return;
    float e0 = emb[(size_t)node * OUT_DIM + lane];
    float e1 = emb[(size_t)node * OUT_DIM + 32 + lane];
    float m = fmaxf(e0, e1);
    #pragma unroll
    for (int o = 16; o; o >>= 1) m = fmaxf(m, __shfl_xor_sync(0xffffffffu, m, o));
    float s = expf(e0 - m) + expf(e1 - m);
    #pragma unroll
    for (int o = 16; o; o >>= 1) s += __shfl_xor_sync(0xffffffffu, s, o);
    float lse = m + logf(s);
    out[(size_t)node * OUT_DIM + lane]      = e0 - lse;
    out[(size_t)node * OUT_DIM + 32 + lane] = e1 - lse;
}

// ---------------- launch ----------------
extern "C" void kernel_launch(void* const* d_in, const int* in_sizes, int n_in,
                              void* d_out, int out_size)
{
    const float* x     = (const float*)d_in[0];
    const int*   ei    = (const int*)  d_in[1];
    const float* t1_w  = (const float*)d_in[2];
    const float* t1_b  = (const float*)d_in[3];
    const float* t2_w  = (const float*)d_in[4];
    const float* t2_b  = (const float*)d_in[5];
    const float* att_l = (const float*)d_in[6];
    const float* att_r = (const float*)d_in[7];
    (void)in_sizes; (void)n_in; (void)out_size;

    const int* src = ei;
    const int* dst = ei + N_EDGES;

    float *h0, *hA, *hB;
    cudaGetSymbolAddress((void**)&h0, g_h0);
    cudaGetSymbolAddress((void**)&hA, g_hA);
    cudaGetSymbolAddress((void**)&hB, g_hB);

    float* outp = (float*)d_out;                              // [50000, 64] log_softmax
    float* emb  = (float*)d_out + (size_t)N_NODES * OUT_DIM;  // [50000, 64] emb

    // CSR build
    zero_deg_kernel<<<(N_NODES + 255) / 256, 256>>>();
    hist_kernel<<<(N_EDGES + 255) / 256, 256>>>(dst);
    scan_kernel<<<1, 1024>>>();
    scatter_kernel<<<(N_EDGES + 255) / 256, 256>>>(src, dst);

    // GEMM1 + relu -> raw (h0)
    gemm1_relu_kernel<<<(N_NODES + 127) / 128, 256>>>(x, t1_w, t1_b, h0);

    // 3 FAConv layers: h0 -> hA -> hB -> hA
    const int warp_blocks = (N_NODES * 32 + 255) / 256;
    const float* cur = h0;
    float* bufs[3] = {hA, hB, hA};
    for (int l = 0; l < 3; l++) {
        alar_kernel<<<warp_blocks, 256>>>(cur, att_l + l * HIDDEN, att_r + l * HIDDEN);
        agg_kernel<<<warp_blocks, 256>>>(cur, h0, bufs[l]);
        cur = bufs[l];
    }

    // GEMM2 -> emb (second half of d_out), then log_softmax -> first half
    gemm2_kernel<<<(N_NODES + 127) / 128, 256>>>(cur, t2_w, t2_b, emb);
    logsoftmax_kernel<<<warp_blocks, 256>>>(emb, outp);
}

// round 6
// speedup vs baseline: 1.2023x; 1.2023x over previous
#include <cuda_runtime.h>
#include <math.h>

#define N_NODES 50000
#define N_EDGES 600000
#define IN_DIM  512
#define HIDDEN  128
#define OUT_DIM 64
#define EPS     0.1f

// ---------------- scratch (device globals; no allocation allowed) ----------------
__device__ float g_h0[(size_t)N_NODES * HIDDEN];   // raw (post-relu GEMM1 output)
__device__ float g_hA[(size_t)N_NODES * HIDDEN];
__device__ float g_hB[(size_t)N_NODES * HIDDEN];
__device__ float g_al[N_NODES];
__device__ float g_ar[N_NODES];
__device__ float g_dinv[N_NODES];
__device__ int   g_deg[N_NODES];
__device__ int   g_ptr[N_NODES + 1];
__device__ int   g_fill[N_NODES];
__device__ int   g_csr_src[N_EDGES];
__device__ int   g_csr_dst[N_EDGES];
__device__ float g_w[N_EDGES];

// ---------------- helpers ----------------
__device__ __forceinline__ float tf32r(float f) {
    unsigned u;
    asm("cvt.rna.tf32.f32 %0, %1;" : "=r"(u) : "f"(f));
    return __uint_as_float(u);
}

__device__ __forceinline__ void mma_tf32(float c[4],
    unsigned a0, unsigned a1, unsigned a2, unsigned a3,
    unsigned b0, unsigned b1)
{
    asm volatile(
        "mma.sync.aligned.m16n8k8.row.col.f32.tf32.tf32.f32 "
        "{%0,%1,%2,%3}, {%4,%5,%6,%7}, {%8,%9}, {%0,%1,%2,%3};"
        : "+f"(c[0]), "+f"(c[1]), "+f"(c[2]), "+f"(c[3])
        : "r"(a0), "r"(a1), "r"(a2), "r"(a3), "r"(b0), "r"(b1));
}

// ---------------- CSR build ----------------
__global__ void zero_deg_kernel() {
    int i = blockIdx.x * blockDim.x + threadIdx.x;
    if (i < N_NODES) g_deg[i] = 0;
}

__global__ void hist_kernel(const int* __restrict__ dst) {
    int e = blockIdx.x * blockDim.x + threadIdx.x;
    if (e < N_EDGES) atomicAdd(&g_deg[dst[e]], 1);
}

// single-block exclusive scan over 50000 degrees; also fills g_fill and g_dinv
__global__ void scan_kernel() {
    __shared__ int partial[1024];
    const int t = threadIdx.x;
    const int CH = (N_NODES + 1023) / 1024;   // 49
    int beg = t * CH;
    int sum = 0;
    for (int i = 0; i < CH; i++) {
        int idx = beg + i;
        if (idx < N_NODES) sum += g_deg[idx];
    }
    partial[t] = sum;
    __syncthreads();
    if (t == 0) {
        int run = 0;
        for (int i = 0; i < 1024; i++) { int v = partial[i]; partial[i] = run; run += v; }
    }
    __syncthreads();
    int run = partial[t];
    for (int i = 0; i < CH; i++) {
        int idx = beg + i;
        if (idx < N_NODES) {
            g_ptr[idx]  = run;
            g_fill[idx] = run;
            int d = g_deg[idx];
            g_dinv[idx] = (d > 0) ? rsqrtf((float)d) : 0.0f;
            run += d;
        }
    }
    if (t == 0) g_ptr[N_NODES] = N_EDGES;
}

__global__ void scatter_kernel(const int* __restrict__ src, const int* __restrict__ dst) {
    int e = blockIdx.x * blockDim.x + threadIdx.x;
    if (e < N_EDGES) {
        int d = dst[e];
        int p = atomicAdd(&g_fill[d], 1);
        g_csr_src[p] = src[e];
        g_csr_dst[p] = d;
    }
}

// ---------------- GEMM1 (tf32 tensor): h = relu(x @ w1^T + b1) ----------------
// [50000,512] x [128,512]^T -> [50000,128]
// BM=64, BN=128, BK=32, 256 threads = 8 warps (2 along M x 4 along N), warp tile 32x32
__global__ __launch_bounds__(256) void gemm1_tf32_kernel(
    const float* __restrict__ x, const float* __restrict__ w,
    const float* __restrict__ bias, float* __restrict__ out)
{
    __shared__ float As[64][36];
    __shared__ float Bs[128][36];
    const int bm   = blockIdx.x * 64;
    const int tid  = threadIdx.x;
    const int wid  = tid >> 5;
    const int lane = tid & 31;
    const int wm   = wid & 1;          // 0..1
    const int wn   = wid >> 1;         // 0..3
    const int g    = lane >> 2;        // groupID 0..7
    const int t    = lane & 3;         // thread-in-group 0..3

    float acc[2][4][4];
    #pragma unroll
    for (int i = 0; i < 2; i++)
        #pragma unroll
        for (int j = 0; j < 4; j++)
            #pragma unroll
            for (int k = 0; k < 4; k++) acc[i][j][k] = 0.0f;

    for (int kb = 0; kb < IN_DIM; kb += 32) {
        // load A tile (64x32), converted to tf32
        #pragma unroll
        for (int i = 0; i < 2; i++) {
            int idx = tid + 256 * i;        // 0..511
            int row = idx >> 3;             // 0..63
            int c4  = (idx & 7) * 4;        // 0..28
            int gm  = bm + row;
            float4 v = make_float4(0.f, 0.f, 0.f, 0.f);
            if (gm < N_NODES)
                v = *(const float4*)(x + (size_t)gm * IN_DIM + kb + c4);
            As[row][c4 + 0] = tf32r(v.x); As[row][c4 + 1] = tf32r(v.y);
            As[row][c4 + 2] = tf32r(v.z); As[row][c4 + 3] = tf32r(v.w);
        }
        // load B tile (128x32) = w[n][k]
        #pragma unroll
        for (int i = 0; i < 4; i++) {
            int idx = tid + 256 * i;        // 0..1023
            int row = idx >> 3;             // 0..127
            int c4  = (idx & 7) * 4;
            float4 u = *(const float4*)(w + (size_t)row * IN_DIM + kb + c4);
            Bs[row][c4 + 0] = tf32r(u.x); Bs[row][c4 + 1] = tf32r(u.y);
            Bs[row][c4 + 2] = tf32r(u.z); Bs[row][c4 + 3] = tf32r(u.w);
        }
        __syncthreads();

        #pragma unroll
        for (int ks = 0; ks < 4; ks++) {
            const int k8 = ks * 8;
            unsigned a[2][4];
            #pragma unroll
            for (int mt = 0; mt < 2; mt++) {
                int rb = wm * 32 + mt * 16;
                a[mt][0] = __float_as_uint(As[rb + g    ][k8 + t    ]);
                a[mt][1] = __float_as_uint(As[rb + g + 8][k8 + t    ]);
                a[mt][2] = __float_as_uint(As[rb + g    ][k8 + t + 4]);
                a[mt][3] = __float_as_uint(As[rb + g + 8][k8 + t + 4]);
            }
            unsigned b[4][2];
            #pragma unroll
            for (int nt = 0; nt < 4; nt++) {
                int nb = wn * 32 + nt * 8;
                b[nt][0] = __float_as_uint(Bs[nb + g][k8 + t    ]);
                b[nt][1] = __float_as_uint(Bs[nb + g][k8 + t + 4]);
            }
            #pragma unroll
            for (int mt = 0; mt < 2; mt++)
                #pragma unroll
                for (int nt = 0; nt < 4; nt++)
                    mma_tf32(acc[mt][nt], a[mt][0], a[mt][1], a[mt][2], a[mt][3],
                             b[nt][0], b[nt][1]);
        }
        __syncthreads();
    }

    // epilogue: bias + relu
    #pragma unroll
    for (int mt = 0; mt < 2; mt++) {
        int r0 = bm + wm * 32 + mt * 16 + g;
        int r1 = r0 + 8;
        #pragma unroll
        for (int nt = 0; nt < 4; nt++) {
            int c = wn * 32 + nt * 8 + t * 2;
            float b0 = bias[c], b1 = bias[c + 1];
            if (r0 < N_NODES) {
                out[(size_t)r0 * HIDDEN + c    ] = fmaxf(acc[mt][nt][0] + b0, 0.0f);
                out[(size_t)r0 * HIDDEN + c + 1] = fmaxf(acc[mt][nt][1] + b1, 0.0f);
            }
            if (r1 < N_NODES) {
                out[(size_t)r1 * HIDDEN + c    ] = fmaxf(acc[mt][nt][2] + b0, 0.0f);
                out[(size_t)r1 * HIDDEN + c + 1] = fmaxf(acc[mt][nt][3] + b1, 0.0f);
            }
        }
    }
}

// ---------------- GEMM2 (tf32 tensor): emb = h @ w2^T + b2 ----------------
// [50000,128] x [64,128]^T -> [50000,64]
// BM=64, BN=64, BK=32, 256 threads = 8 warps (2 x 4), warp tile 32x16
__global__ __launch_bounds__(256) void gemm2_tf32_kernel(
    const float* __restrict__ h, const float* __restrict__ w2,
    const float* __restrict__ b2, float* __restrict__ emb)
{
    __shared__ float As[64][36];
    __shared__ float Bs[64][36];
    const int bm   = blockIdx.x * 64;
    const int tid  = threadIdx.x;
    const int wid  = tid >> 5;
    const int lane = tid & 31;
    const int wm   = wid & 1;
    const int wn   = wid >> 1;         // 0..3, warpN = 16
    const int g    = lane >> 2;
    const int t    = lane & 3;

    float acc[2][2][4];
    #pragma unroll
    for (int i = 0; i < 2; i++)
        #pragma unroll
        for (int j = 0; j < 2; j++)
            #pragma unroll
            for (int k = 0; k < 4; k++) acc[i][j][k] = 0.0f;

    for (int kb = 0; kb < HIDDEN; kb += 32) {
        #pragma unroll
        for (int i = 0; i < 2; i++) {
            int idx = tid + 256 * i;        // 0..511
            int row = idx >> 3;             // 0..63
            int c4  = (idx & 7) * 4;
            int gm  = bm + row;
            float4 v = make_float4(0.f, 0.f, 0.f, 0.f);
            if (gm < N_NODES)
                v = *(const float4*)(h + (size_t)gm * HIDDEN + kb + c4);
            As[row][c4 + 0] = tf32r(v.x); As[row][c4 + 1] = tf32r(v.y);
            As[row][c4 + 2] = tf32r(v.z); As[row][c4 + 3] = tf32r(v.w);
        }
        #pragma unroll
        for (int i = 0; i < 2; i++) {
            int idx = tid + 256 * i;        // 0..511
            int row = idx >> 3;             // 0..63
            int c4  = (idx & 7) * 4;
            float4 u = *(const float4*)(w2 + (size_t)row * HIDDEN + kb + c4);
            Bs[row][c4 + 0] = tf32r(u.x); Bs[row][c4 + 1] = tf32r(u.y);
            Bs[row][c4 + 2] = tf32r(u.z); Bs[row][c4 + 3] = tf32r(u.w);
        }
        __syncthreads();

        #pragma unroll
        for (int ks = 0; ks < 4; ks++) {
            const int k8 = ks * 8;
            unsigned a[2][4];
            #pragma unroll
            for (int mt = 0; mt < 2; mt++) {
                int rb = wm * 32 + mt * 16;
                a[mt][0] = __float_as_uint(As[rb + g    ][k8 + t    ]);
                a[mt][1] = __float_as_uint(As[rb + g + 8][k8 + t    ]);
                a[mt][2] = __float_as_uint(As[rb + g    ][k8 + t + 4]);
                a[mt][3] = __float_as_uint(As[rb + g + 8][k8 + t + 4]);
            }
            unsigned b[2][2];
            #pragma unroll
            for (int nt = 0; nt < 2; nt++) {
                int nb = wn * 16 + nt * 8;
                b[nt][0] = __float_as_uint(Bs[nb + g][k8 + t    ]);
                b[nt][1] = __float_as_uint(Bs[nb + g][k8 + t + 4]);
            }
            #pragma unroll
            for (int mt = 0; mt < 2; mt++)
                #pragma unroll
                for (int nt = 0; nt < 2; nt++)
                    mma_tf32(acc[mt][nt], a[mt][0], a[mt][1], a[mt][2], a[mt][3],
                             b[nt][0], b[nt][1]);
        }
        __syncthreads();
    }

    #pragma unroll
    for (int mt = 0; mt < 2; mt++) {
        int r0 = bm + wm * 32 + mt * 16 + g;
        int r1 = r0 + 8;
        #pragma unroll
        for (int nt = 0; nt < 2; nt++) {
            int c = wn * 16 + nt * 8 + t * 2;
            float b0 = b2[c], b1 = b2[c + 1];
            if (r0 < N_NODES) {
                emb[(size_t)r0 * OUT_DIM + c    ] = acc[mt][nt][0] + b0;
                emb[(size_t)r0 * OUT_DIM + c + 1] = acc[mt][nt][1] + b1;
            }
            if (r1 < N_NODES) {
                emb[(size_t)r1 * OUT_DIM + c    ] = acc[mt][nt][2] + b0;
                emb[(size_t)r1 * OUT_DIM + c + 1] = acc[mt][nt][3] + b1;
            }
        }
    }
}

// ---------------- per-layer: al/ar = h . att ----------------
__global__ void alar_kernel(const float* __restrict__ h,
                            const float* __restrict__ attl,
                            const float* __restrict__ attr)
{
    int gw   = (blockIdx.x * blockDim.x + threadIdx.x) >> 5;
    int lane = threadIdx.x & 31;
    if (gw >= N_NODES) return;
    float4 hv = *((const float4*)(h + (size_t)gw * HIDDEN) + lane);
    float4 lv = ((const float4*)attl)[lane];
    float4 rv = ((const float4*)attr)[lane];
    float sl = hv.x * lv.x + hv.y * lv.y + hv.z * lv.z + hv.w * lv.w;
    float sr = hv.x * rv.x + hv.y * rv.y + hv.z * rv.z + hv.w * rv.w;
    #pragma unroll
    for (int o = 16; o; o >>= 1) {
        sl += __shfl_xor_sync(0xffffffffu, sl, o);
        sr += __shfl_xor_sync(0xffffffffu, sr, o);
    }
    if (lane == 0) { g_al[gw] = sl; g_ar[gw] = sr; }
}

// ---------------- per-layer: edge weights w = tanh(al[s]+ar[d]) * dinv[s]*dinv[d] ----------------
__global__ void weight_kernel() {
    int j = blockIdx.x * blockDim.x + threadIdx.x;
    if (j >= N_EDGES) return;
    int s = g_csr_src[j];
    int d = g_csr_dst[j];
    g_w[j] = tanhf(g_al[s] + g_ar[d]) * (g_dinv[s] * g_dinv[d]);
}

// ---------------- per-layer: aggregation (warp per node, CSR, unroll-4 MLP) ----------------
__global__ void agg_kernel(const float* __restrict__ hcur,
                           const float* __restrict__ raw,
                           float* __restrict__ hnext)
{
    int node = (blockIdx.x * blockDim.x + threadIdx.x) >> 5;
    int lane = threadIdx.x & 31;
    if (node >= N_NODES) return;

    const int beg = g_ptr[node];
    const int end = g_ptr[node + 1];

    float4 rv = *((const float4*)(raw + (size_t)node * HIDDEN) + lane);
    float4 acc = make_float4(EPS * rv.x, EPS * rv.y, EPS * rv.z, EPS * rv.w);

    int j = beg;
    for (; j + 4 <= end; j += 4) {
        int s0 = __ldg(&g_csr_src[j + 0]);
        int s1 = __ldg(&g_csr_src[j + 1]);
        int s2 = __ldg(&g_csr_src[j + 2]);
        int s3 = __ldg(&g_csr_src[j + 3]);
        float w0 = __ldg(&g_w[j + 0]);
        float w1 = __ldg(&g_w[j + 1]);
        float w2 = __ldg(&g_w[j + 2]);
        float w3 = __ldg(&g_w[j + 3]);
        float4 v0 = __ldg((const float4*)(hcur + (size_t)s0 * HIDDEN) + lane);
        float4 v1 = __ldg((const float4*)(hcur + (size_t)s1 * HIDDEN) + lane);
        float4 v2 = __ldg((const float4*)(hcur + (size_t)s2 * HIDDEN) + lane);
        float4 v3 = __ldg((const float4*)(hcur + (size_t)s3 * HIDDEN) + lane);
        acc.x = fmaf(w0, v0.x, acc.x); acc.y = fmaf(w0, v0.y, acc.y);
        acc.z = fmaf(w0, v0.z, acc.z); acc.w = fmaf(w0, v0.w, acc.w);
        acc.x = fmaf(w1, v1.x, acc.x); acc.y = fmaf(w1, v1.y, acc.y);
        acc.z = fmaf(w1, v1.z, acc.z); acc.w = fmaf(w1, v1.w, acc.w);
        acc.x = fmaf(w2, v2.x, acc.x); acc.y = fmaf(w2, v2.y, acc.y);
        acc.z = fmaf(w2, v2.z, acc.z); acc.w = fmaf(w2, v2.w, acc.w);
        acc.x = fmaf(w3, v3.x, acc.x); acc.y = fmaf(w3, v3.y, acc.y);
        acc.z = fmaf(w3, v3.z, acc.z); acc.w = fmaf(w3, v3.w, acc.w);
    }
    for (; j < end; j++) {
        int s = __ldg(&g_csr_src[j]);
        float wgt = __ldg(&g_w[j]);
        float4 hs = __ldg((const float4*)(hcur + (size_t)s * HIDDEN) + lane);
        acc.x = fmaf(wgt, hs.x, acc.x);
        acc.y = fmaf(wgt, hs.y, acc.y);
        acc.z = fmaf(wgt, hs.z, acc.z);
        acc.w = fmaf(wgt, hs.w, acc.w);
    }
    *((float4*)(hnext + (size_t)node * HIDDEN) + lane) = acc;
}

// ---------------- log_softmax over 64 cols (warp per node) ----------------
__global__ void logsoftmax_kernel(const float* __restrict__ emb, float* __restrict__ out)
{
    int node = (blockIdx.x * blockDim.x + threadIdx.x) >> 5;
    int lane = threadIdx.x & 31;
    if (node >= N_NODES) return;
    float e0 = emb[(size_t)node * OUT_DIM + lane];
    float e1 = emb[(size_t)node * OUT_DIM + 32 + lane];
    float m = fmaxf(e0, e1);
    #pragma unroll
    for (int o = 16; o; o >>= 1) m = fmaxf(m, __shfl_xor_sync(0xffffffffu, m, o));
    float s = expf(e0 - m) + expf(e1 - m);
    #pragma unroll
    for (int o = 16; o; o >>= 1) s += __shfl_xor_sync(0xffffffffu, s, o);
    float lse = m + logf(s);
    out[(size_t)node * OUT_DIM + lane]      = e0 - lse;
    out[(size_t)node * OUT_DIM + 32 + lane] = e1 - lse;
}

// ---------------- launch ----------------
extern "C" void kernel_launch(void* const* d_in, const int* in_sizes, int n_in,
                              void* d_out, int out_size)
{
    const float* x     = (const float*)d_in[0];
    const int*   ei    = (const int*)  d_in[1];
    const float* t1_w  = (const float*)d_in[2];
    const float* t1_b  = (const float*)d_in[3];
    const float* t2_w  = (const float*)d_in[4];
    const float* t2_b  = (const float*)d_in[5];
    const float* att_l = (const float*)d_in[6];
    const float* att_r = (const float*)d_in[7];
    (void)in_sizes; (void)n_in; (void)out_size;

    const int* src = ei;
    const int* dst = ei + N_EDGES;

    float *h0, *hA, *hB;
    cudaGetSymbolAddress((void**)&h0, g_h0);
    cudaGetSymbolAddress((void**)&hA, g_hA);
    cudaGetSymbolAddress((void**)&hB, g_hB);

    float* outp = (float*)d_out;                              // [50000, 64] log_softmax
    float* emb  = (float*)d_out + (size_t)N_NODES * OUT_DIM;  // [50000, 64] emb

    // CSR build
    zero_deg_kernel<<<(N_NODES + 255) / 256, 256>>>();
    hist_kernel<<<(N_EDGES + 255) / 256, 256>>>(dst);
    scan_kernel<<<1, 1024>>>();
    scatter_kernel<<<(N_EDGES + 255) / 256, 256>>>(src, dst);

    // GEMM1 + relu -> raw (h0), tf32 tensor path
    gemm1_tf32_kernel<<<(N_NODES + 63) / 64, 256>>>(x, t1_w, t1_b, h0);

    // 3 FAConv layers: h0 -> hA -> hB -> hA
    const int warp_blocks = (N_NODES * 32 + 255) / 256;
    const int edge_blocks = (N_EDGES + 255) / 256;
    const float* cur = h0;
    float* bufs[3] = {hA, hB, hA};
    for (int l = 0; l < 3; l++) {
        alar_kernel<<<warp_blocks, 256>>>(cur, att_l + l * HIDDEN, att_r + l * HIDDEN);
        weight_kernel<<<edge_blocks, 256>>>();
        agg_kernel<<<warp_blocks, 256>>>(cur, h0, bufs[l]);
        cur = bufs[l];
    }

    // GEMM2 -> emb (second half of d_out), then log_softmax -> first half
    gemm2_tf32_kernel<<<(N_NODES + 63) / 64, 256>>>(cur, t2_w, t2_b, emb);
    logsoftmax_kernel<<<warp_blocks, 256>>>(emb, outp);
}

// round 10
// speedup vs baseline: 1.3524x; 1.1249x over previous
#include <cuda_runtime.h>
#include <math.h>

#define N_NODES 50000
#define N_EDGES 600000
#define IN_DIM  512
#define HIDDEN  128
#define OUT_DIM 64
#define EPS     0.1f

// ---------------- scratch (device globals; no allocation allowed) ----------------
__device__ float g_h0[(size_t)N_NODES * HIDDEN];   // raw (post-relu GEMM1 output)
__device__ float g_hA[(size_t)N_NODES * HIDDEN];
__device__ float g_hB[(size_t)N_NODES * HIDDEN];
__device__ float g_al[N_NODES];
__device__ float g_ar[N_NODES];
__device__ float g_dinv[N_NODES];
__device__ int   g_deg[N_NODES];
__device__ int   g_ptr[N_NODES + 1];
__device__ int   g_fill[N_NODES];
__device__ int   g_csr_src[N_EDGES];
__device__ int   g_csr_dst[N_EDGES];
__device__ float g_w[N_EDGES];

// ---------------- helpers ----------------
__device__ __forceinline__ unsigned tf32u(float f) {
    unsigned u;
    asm("cvt.rna.tf32.f32 %0, %1;" : "=r"(u) : "f"(f));
    return u;
}

__device__ __forceinline__ void mma_tf32(float c[4],
    unsigned a0, unsigned a1, unsigned a2, unsigned a3,
    unsigned b0, unsigned b1)
{
    asm volatile(
        "mma.sync.aligned.m16n8k8.row.col.f32.tf32.tf32.f32 "
        "{%0,%1,%2,%3}, {%4,%5,%6,%7}, {%8,%9}, {%0,%1,%2,%3};"
        : "+f"(c[0]), "+f"(c[1]), "+f"(c[2]), "+f"(c[3])
        : "r"(a0), "r"(a1), "r"(a2), "r"(a3), "r"(b0), "r"(b1));
}

__device__ __forceinline__ void cp16(float* smem, const float* gmem) {
    unsigned s = (unsigned)__cvta_generic_to_shared(smem);
    asm volatile("cp.async.cg.shared.global [%0], [%1], 16;\n" :: "r"(s), "l"(gmem));
}
__device__ __forceinline__ void cp_commit() {
    asm volatile("cp.async.commit_group;\n");
}
template <int N>
__device__ __forceinline__ void cp_wait() {
    asm volatile("cp.async.wait_group %0;\n" :: "n"(N));
}

// ---------------- CSR build ----------------
__global__ void hist_kernel(const int* __restrict__ dst) {
    int e = blockIdx.x * blockDim.x + threadIdx.x;
    if (e < N_EDGES) atomicAdd(&g_deg[dst[e]], 1);
}

// single-block exclusive scan over 50000 degrees; also fills g_fill and g_dinv
__global__ void scan_kernel() {
    __shared__ int partial[1024];
    const int t = threadIdx.x;
    const int CH = (N_NODES + 1023) / 1024;   // 49
    int beg = t * CH;
    int sum = 0;
    for (int i = 0; i < CH; i++) {
        int idx = beg + i;
        if (idx < N_NODES) sum += g_deg[idx];
    }
    partial[t] = sum;
    __syncthreads();
    if (t == 0) {
        int run = 0;
        for (int i = 0; i < 1024; i++) { int v = partial[i]; partial[i] = run; run += v; }
    }
    __syncthreads();
    int run = partial[t];
    for (int i = 0; i < CH; i++) {
        int idx = beg + i;
        if (idx < N_NODES) {
            g_ptr[idx]  = run;
            g_fill[idx] = run;
            int d = g_deg[idx];
            g_dinv[idx] = (d > 0) ? rsqrtf((float)d) : 0.0f;
            run += d;
        }
    }
    if (t == 0) g_ptr[N_NODES] = N_EDGES;
}

__global__ void scatter_kernel(const int* __restrict__ src, const int* __restrict__ dst) {
    int e = blockIdx.x * blockDim.x + threadIdx.x;
    if (e < N_EDGES) {
        int d = dst[e];
        int p = atomicAdd(&g_fill[d], 1);
        g_csr_src[p] = src[e];
        g_csr_dst[p] = d;
    }
}

// ---------------- GEMM1 (tf32 tensor, cp.async double-buffered) ----------------
// h = relu(x @ w1^T + b1): [50000,512] x [128,512]^T -> [50000,128]
// BM=128, BN=128, BK=16, 256 threads = 8 warps (2 along M x 4 along N),
// warp tile 64x32 (mt 0..3 of 16 rows, nt 0..3 of 8 cols)
#define G1_BK 16
#define G1_PAD 20
__global__ __launch_bounds__(256) void gemm1_tf32_kernel(
    const float* __restrict__ x, const float* __restrict__ w,
    const float* __restrict__ bias, float* __restrict__ out)
{
    __shared__ float As[2][128][G1_PAD];
    __shared__ float Bs[2][128][G1_PAD];
    const int bm   = blockIdx.x * 128;
    const int tid  = threadIdx.x;
    const int wid  = tid >> 5;
    const int lane = tid & 31;
    const int wm   = wid & 1;          // 0..1 (64 rows each)
    const int wn   = wid >> 1;         // 0..3 (32 cols each)
    const int g    = lane >> 2;        // 0..7
    const int t    = lane & 3;         // 0..3

    // per-thread load coords: 2 float4 per tile per matrix
    // float4 id f = tid + 256*i (0..511): row = f>>2 (0..127), c4 = (f&3)*4
    const int lr0 = tid >> 2;
    const int lc  = (tid & 3) * 4;

    float acc[4][4][4];
    #pragma unroll
    for (int i = 0; i < 4; i++)
        #pragma unroll
        for (int j = 0; j < 4; j++)
            #pragma unroll
            for (int k = 0; k < 4; k++) acc[i][j][k] = 0.0f;

    const int NKB = IN_DIM / G1_BK;    // 32

    // prologue: stage 0
    {
        const int kb = 0;
        #pragma unroll
        for (int i = 0; i < 2; i++) {
            int row = lr0 + 64 * i;
            int gm = bm + row;
            // rows >= N_NODES only in the last block; clamp to a valid row (result discarded)
            int gms = (gm < N_NODES) ? gm : (N_NODES - 1);
            cp16(&As[0][row][lc], x + (size_t)gms * IN_DIM + kb + lc);
            cp16(&Bs[0][row][lc], w + (size_t)row * IN_DIM + kb + lc);
        }
        cp_commit();
    }

    int buf = 0;
    for (int kbi = 0; kbi < NKB; kbi++) {
        if (kbi + 1 < NKB) {
            const int kb = (kbi + 1) * G1_BK;
            #pragma unroll
            for (int i = 0; i < 2; i++) {
                int row = lr0 + 64 * i;
                int gm = bm + row;
                int gms = (gm < N_NODES) ? gm : (N_NODES - 1);
                cp16(&As[buf ^ 1][row][lc], x + (size_t)gms * IN_DIM + kb + lc);
                cp16(&Bs[buf ^ 1][row][lc], w + (size_t)row * IN_DIM + kb + lc);
            }
            cp_commit();
            cp_wait<1>();
        } else {
            cp_wait<0>();
        }
        __syncthreads();

        #pragma unroll
        for (int ks = 0; ks < 2; ks++) {
            const int k8 = ks * 8;
            unsigned a[4][4];
            #pragma unroll
            for (int mt = 0; mt < 4; mt++) {
                int rb = wm * 64 + mt * 16;
                a[mt][0] = tf32u(As[buf][rb + g    ][k8 + t    ]);
                a[mt][1] = tf32u(As[buf][rb + g + 8][k8 + t    ]);
                a[mt][2] = tf32u(As[buf][rb + g    ][k8 + t + 4]);
                a[mt][3] = tf32u(As[buf][rb + g + 8][k8 + t + 4]);
            }
            unsigned b[4][2];
            #pragma unroll
            for (int nt = 0; nt < 4; nt++) {
                int nb = wn * 32 + nt * 8;
                b[nt][0] = tf32u(Bs[buf][nb + g][k8 + t    ]);
                b[nt][1] = tf32u(Bs[buf][nb + g][k8 + t + 4]);
            }
            #pragma unroll
            for (int mt = 0; mt < 4; mt++)
                #pragma unroll
                for (int nt = 0; nt < 4; nt++)
                    mma_tf32(acc[mt][nt], a[mt][0], a[mt][1], a[mt][2], a[mt][3],
                             b[nt][0], b[nt][1]);
        }
        __syncthreads();
        buf ^= 1;
    }

    // epilogue: bias + relu
    #pragma unroll
    for (int mt = 0; mt < 4; mt++) {
        int r0 = bm + wm * 64 + mt * 16 + g;
        int r1 = r0 + 8;
        #pragma unroll
        for (int nt = 0; nt < 4; nt++) {
            int c = wn * 32 + nt * 8 + t * 2;
            float b0 = bias[c], b1 = bias[c + 1];
            if (r0 < N_NODES) {
                out[(size_t)r0 * HIDDEN + c    ] = fmaxf(acc[mt][nt][0] + b0, 0.0f);
                out[(size_t)r0 * HIDDEN + c + 1] = fmaxf(acc[mt][nt][1] + b1, 0.0f);
            }
            if (r1 < N_NODES) {
                out[(size_t)r1 * HIDDEN + c    ] = fmaxf(acc[mt][nt][2] + b0, 0.0f);
                out[(size_t)r1 * HIDDEN + c + 1] = fmaxf(acc[mt][nt][3] + b1, 0.0f);
            }
        }
    }
}

// ---------------- GEMM2 (tf32 tensor): emb = h @ w2^T + b2 ----------------
// [50000,128] x [64,128]^T -> [50000,64]
__global__ __launch_bounds__(256) void gemm2_tf32_kernel(
    const float* __restrict__ h, const float* __restrict__ w2,
    const float* __restrict__ b2, float* __restrict__ emb)
{
    __shared__ float As[64][36];
    __shared__ float Bs[64][36];
    const int bm   = blockIdx.x * 64;
    const int tid  = threadIdx.x;
    const int wid  = tid >> 5;
    const int lane = tid & 31;
    const int wm   = wid & 1;
    const int wn   = wid >> 1;         // 0..3, warpN = 16
    const int g    = lane >> 2;
    const int t    = lane & 3;

    float acc[2][2][4];
    #pragma unroll
    for (int i = 0; i < 2; i++)
        #pragma unroll
        for (int j = 0; j < 2; j++)
            #pragma unroll
            for (int k = 0; k < 4; k++) acc[i][j][k] = 0.0f;

    for (int kb = 0; kb < HIDDEN; kb += 32) {
        #pragma unroll
        for (int i = 0; i < 2; i++) {
            int idx = tid + 256 * i;
            int row = idx >> 3;
            int c4  = (idx & 7) * 4;
            int gm  = bm + row;
            float4 v = make_float4(0.f, 0.f, 0.f, 0.f);
            if (gm < N_NODES)
                v = *(const float4*)(h + (size_t)gm * HIDDEN + kb + c4);
            As[row][c4 + 0] = v.x; As[row][c4 + 1] = v.y;
            As[row][c4 + 2] = v.z; As[row][c4 + 3] = v.w;
        }
        #pragma unroll
        for (int i = 0; i < 2; i++) {
            int idx = tid + 256 * i;
            int row = idx >> 3;
            int c4  = (idx & 7) * 4;
            float4 u = *(const float4*)(w2 + (size_t)row * HIDDEN + kb + c4);
            Bs[row][c4 + 0] = u.x; Bs[row][c4 + 1] = u.y;
            Bs[row][c4 + 2] = u.z; Bs[row][c4 + 3] = u.w;
        }
        __syncthreads();

        #pragma unroll
        for (int ks = 0; ks < 4; ks++) {
            const int k8 = ks * 8;
            unsigned a[2][4];
            #pragma unroll
            for (int mt = 0; mt < 2; mt++) {
                int rb = wm * 32 + mt * 16;
                a[mt][0] = tf32u(As[rb + g    ][k8 + t    ]);
                a[mt][1] = tf32u(As[rb + g + 8][k8 + t    ]);
                a[mt][2] = tf32u(As[rb + g    ][k8 + t + 4]);
                a[mt][3] = tf32u(As[rb + g + 8][k8 + t + 4]);
            }
            unsigned b[2][2];
            #pragma unroll
            for (int nt = 0; nt < 2; nt++) {
                int nb = wn * 16 + nt * 8;
                b[nt][0] = tf32u(Bs[nb + g][k8 + t    ]);
                b[nt][1] = tf32u(Bs[nb + g][k8 + t + 4]);
            }
            #pragma unroll
            for (int mt = 0; mt < 2; mt++)
                #pragma unroll
                for (int nt = 0; nt < 2; nt++)
                    mma_tf32(acc[mt][nt], a[mt][0], a[mt][1], a[mt][2], a[mt][3],
                             b[nt][0], b[nt][1]);
        }
        __syncthreads();
    }

    #pragma unroll
    for (int mt = 0; mt < 2; mt++) {
        int r0 = bm + wm * 32 + mt * 16 + g;
        int r1 = r0 + 8;
        #pragma unroll
        for (int nt = 0; nt < 2; nt++) {
            int c = wn * 16 + nt * 8 + t * 2;
            float b0 = b2[c], b1 = b2[c + 1];
            if (r0 < N_NODES) {
                emb[(size_t)r0 * OUT_DIM + c    ] = acc[mt][nt][0] + b0;
                emb[(size_t)r0 * OUT_DIM + c + 1] = acc[mt][nt][1] + b1;
            }
            if (r1 < N_NODES) {
                emb[(size_t)r1 * OUT_DIM + c    ] = acc[mt][nt][2] + b0;
                emb[(size_t)r1 * OUT_DIM + c + 1] = acc[mt][nt][3] + b1;
            }
        }
    }
}

// ---------------- layer-0 alar: al/ar = h . att ----------------
__global__ void alar_kernel(const float* __restrict__ h,
                            const float* __restrict__ attl,
                            const float* __restrict__ attr)
{
    int gw   = (blockIdx.x * blockDim.x + threadIdx.x) >> 5;
    int lane = threadIdx.x & 31;
    if (gw >= N_NODES) return;
    float4 hv = *((const float4*)(h + (size_t)gw * HIDDEN) + lane);
    float4 lv = ((const float4*)attl)[lane];
    float4 rv = ((const float4*)attr)[lane];
    float sl = hv.x * lv.x + hv.y * lv.y + hv.z * lv.z + hv.w * lv.w;
    float sr = hv.x * rv.x + hv.y * rv.y + hv.z * rv.z + hv.w * rv.w;
    #pragma unroll
    for (int o = 16; o; o >>= 1) {
        sl += __shfl_xor_sync(0xffffffffu, sl, o);
        sr += __shfl_xor_sync(0xffffffffu, sr, o);
    }
    if (lane == 0) { g_al[gw] = sl; g_ar[gw] = sr; }
}

// ---------------- per-layer: edge weights w = tanh(al[s]+ar[d]) * dinv[s]*dinv[d] ----------------
__global__ void weight_kernel() {
    int j = blockIdx.x * blockDim.x + threadIdx.x;
    if (j >= N_EDGES) return;
    int s = g_csr_src[j];
    int d = g_csr_dst[j];
    g_w[j] = tanhf(g_al[s] + g_ar[d]) * (g_dinv[s] * g_dinv[d]);
}

// ---------------- per-layer: aggregation (warp/node, CSR, unroll-4, fused next-layer alar) ----------------
__global__ void agg_kernel(const float* __restrict__ hcur,
                           const float* __restrict__ raw,
                           float* __restrict__ hnext,
                           const float* __restrict__ attl,   // next layer (null = skip)
                           const float* __restrict__ attr)
{
    int node = (blockIdx.x * blockDim.x + threadIdx.x) >> 5;
    int lane = threadIdx.x & 31;
    if (node >= N_NODES) return;

    const int beg = g_ptr[node];
    const int end = g_ptr[node + 1];

    float4 rv = *((const float4*)(raw + (size_t)node * HIDDEN) + lane);
    float4 acc = make_float4(EPS * rv.x, EPS * rv.y, EPS * rv.z, EPS * rv.w);

    int j = beg;
    for (; j + 4 <= end; j += 4) {
        int s0 = __ldg(&g_csr_src[j + 0]);
        int s1 = __ldg(&g_csr_src[j + 1]);
        int s2 = __ldg(&g_csr_src[j + 2]);
        int s3 = __ldg(&g_csr_src[j + 3]);
        float w0 = __ldg(&g_w[j + 0]);
        float w1 = __ldg(&g_w[j + 1]);
        float w2 = __ldg(&g_w[j + 2]);
        float w3 = __ldg(&g_w[j + 3]);
        float4 v0 = __ldg((const float4*)(hcur + (size_t)s0 * HIDDEN) + lane);
        float4 v1 = __ldg((const float4*)(hcur + (size_t)s1 * HIDDEN) + lane);
        float4 v2 = __ldg((const float4*)(hcur + (size_t)s2 * HIDDEN) + lane);
        float4 v3 = __ldg((const float4*)(hcur + (size_t)s3 * HIDDEN) + lane);
        acc.x = fmaf(w0, v0.x, acc.x); acc.y = fmaf(w0, v0.y, acc.y);
        acc.z = fmaf(w0, v0.z, acc.z); acc.w = fmaf(w0, v0.w, acc.w);
        acc.x = fmaf(w1, v1.x, acc.x); acc.y = fmaf(w1, v1.y, acc.y);
        acc.z = fmaf(w1, v1.z, acc.z); acc.w = fmaf(w1, v1.w, acc.w);
        acc.x = fmaf(w2, v2.x, acc.x); acc.y = fmaf(w2, v2.y, acc.y);
        acc.z = fmaf(w2, v2.z, acc.z); acc.w = fmaf(w2, v2.w, acc.w);
        acc.x = fmaf(w3, v3.x, acc.x); acc.y = fmaf(w3, v3.y, acc.y);
        acc.z = fmaf(w3, v3.z, acc.z); acc.w = fmaf(w3, v3.w, acc.w);
    }
    for (; j < end; j++) {
        int s = __ldg(&g_csr_src[j]);
        float wgt = __ldg(&g_w[j]);
        float4 hs = __ldg((const float4*)(hcur + (size_t)s * HIDDEN) + lane);
        acc.x = fmaf(wgt, hs.x, acc.x);
        acc.y = fmaf(wgt, hs.y, acc.y);
        acc.z = fmaf(wgt, hs.z, acc.z);
        acc.w = fmaf(wgt, hs.w, acc.w);
    }
    *((float4*)(hnext + (size_t)node * HIDDEN) + lane) = acc;

    // fused alar for the next layer
    if (attl != nullptr) {
        float4 lv = ((const float4*)attl)[lane];
        float4 rv2 = ((const float4*)attr)[lane];
        float sl = acc.x * lv.x + acc.y * lv.y + acc.z * lv.z + acc.w * lv.w;
        float sr = acc.x * rv2.x + acc.y * rv2.y + acc.z * rv2.z + acc.w * rv2.w;
        #pragma unroll
        for (int o = 16; o; o >>= 1) {
            sl += __shfl_xor_sync(0xffffffffu, sl, o);
            sr += __shfl_xor_sync(0xffffffffu, sr, o);
        }
        if (lane == 0) { g_al[node] = sl; g_ar[node] = sr; }
    }
}

// ---------------- log_softmax over 64 cols (warp per node) ----------------
__global__ void logsoftmax_kernel(const float* __restrict__ emb, float* __restrict__ out)
{
    int node = (blockIdx.x * blockDim.x + threadIdx.x) >> 5;
    int lane = threadIdx.x & 31;
    if (node >= N_NODES) return;
    float e0 = emb[(size_t)node * OUT_DIM + lane];
    float e1 = emb[(size_t)node * OUT_DIM + 32 + lane];
    float m = fmaxf(e0, e1);
    #pragma unroll
    for (int o = 16; o; o >>= 1) m = fmaxf(m, __shfl_xor_sync(0xffffffffu, m, o));
    float s = expf(e0 - m) + expf(e1 - m);
    #pragma unroll
    for (int o = 16; o; o >>= 1) s += __shfl_xor_sync(0xffffffffu, s, o);
    float lse = m + logf(s);
    out[(size_t)node * OUT_DIM + lane]      = e0 - lse;
    out[(size_t)node * OUT_DIM + 32 + lane] = e1 - lse;
}

// ---------------- launch ----------------
extern "C" void kernel_launch(void* const* d_in, const int* in_sizes, int n_in,
                              void* d_out, int out_size)
{
    const float* x     = (const float*)d_in[0];
    const int*   ei    = (const int*)  d_in[1];
    const float* t1_w  = (const float*)d_in[2];
    const float* t1_b  = (const float*)d_in[3];
    const float* t2_w  = (const float*)d_in[4];
    const float* t2_b  = (const float*)d_in[5];
    const float* att_l = (const float*)d_in[6];
    const float* att_r = (const float*)d_in[7];
    (void)in_sizes; (void)n_in; (void)out_size;

    const int* src = ei;
    const int* dst = ei + N_EDGES;

    float *h0, *hA, *hB;
    int* degp;
    cudaGetSymbolAddress((void**)&h0, g_h0);
    cudaGetSymbolAddress((void**)&hA, g_hA);
    cudaGetSymbolAddress((void**)&hB, g_hB);
    cudaGetSymbolAddress((void**)&degp, g_deg);

    float* outp = (float*)d_out;                              // [50000, 64] log_softmax
    float* emb  = (float*)d_out + (size_t)N_NODES * OUT_DIM;  // [50000, 64] emb

    // CSR build
    cudaMemsetAsync(degp, 0, N_NODES * sizeof(int));
    hist_kernel<<<(N_EDGES + 255) / 256, 256>>>(dst);
    scan_kernel<<<1, 1024>>>();
    scatter_kernel<<<(N_EDGES + 255) / 256, 256>>>(src, dst);

    // GEMM1 + relu -> raw (h0), tf32 tensor path with cp.async double buffering
    gemm1_tf32_kernel<<<(N_NODES + 127) / 128, 256>>>(x, t1_w, t1_b, h0);

    const int warp_blocks = (N_NODES * 32 + 255) / 256;
    const int edge_blocks = (N_EDGES + 255) / 256;

    // layer 0 alar (h0), then 3 layers with alar fused into agg epilogue
    alar_kernel<<<warp_blocks, 256>>>(h0, att_l + 0 * HIDDEN, att_r + 0 * HIDDEN);

    weight_kernel<<<edge_blocks, 256>>>();
    agg_kernel<<<warp_blocks, 256>>>(h0, h0, hA, att_l + 1 * HIDDEN, att_r + 1 * HIDDEN);

    weight_kernel<<<edge_blocks, 256>>>();
    agg_kernel<<<warp_blocks, 256>>>(hA, h0, hB, att_l + 2 * HIDDEN, att_r + 2 * HIDDEN);

    weight_kernel<<<edge_blocks, 256>>>();
    agg_kernel<<<warp_blocks, 256>>>(hB, h0, hA, nullptr, nullptr);

    // GEMM2 -> emb (second half of d_out), then log_softmax -> first half
    gemm2_tf32_kernel<<<(N_NODES + 63) / 64, 256>>>(hA, t2_w, t2_b, emb);
    logsoftmax_kernel<<<warp_blocks, 256>>>(emb, outp);
}

// round 13
// speedup vs baseline: 1.3910x; 1.0285x over previous
#include <cuda_runtime.h>
#include <math.h>

#define N_NODES 50000
#define N_EDGES 600000
#define IN_DIM  512
#define HIDDEN  128
#define OUT_DIM 64
#define EPS     0.1f

// ---------------- scratch (device globals; no allocation allowed) ----------------
__device__ float g_h0[(size_t)N_NODES * HIDDEN];   // raw (post-relu GEMM1 output)
__device__ float g_hA[(size_t)N_NODES * HIDDEN];
__device__ float g_hB[(size_t)N_NODES * HIDDEN];
__device__ float g_al[N_NODES];
__device__ float g_ar[N_NODES];
__device__ float g_dinv[N_NODES];
__device__ int   g_deg[N_NODES];
__device__ int   g_ptr[N_NODES + 1];
__device__ int   g_fill[N_NODES];
__device__ int   g_csr_src[N_EDGES];
__device__ int   g_csr_dst[N_EDGES];
__device__ int2  g_ew[N_EDGES];                    // packed {src, w bits}
__device__ float g_w1r[HIDDEN * IN_DIM];           // tf32-pre-rounded t1_w

// ---------------- helpers ----------------
__device__ __forceinline__ unsigned tf32u(float f) {
    unsigned u;
    asm("cvt.rna.tf32.f32 %0, %1;" : "=r"(u) : "f"(f));
    return u;
}

__device__ __forceinline__ void mma_tf32(float c[4],
    unsigned a0, unsigned a1, unsigned a2, unsigned a3,
    unsigned b0, unsigned b1)
{
    asm volatile(
        "mma.sync.aligned.m16n8k8.row.col.f32.tf32.tf32.f32 "
        "{%0,%1,%2,%3}, {%4,%5,%6,%7}, {%8,%9}, {%0,%1,%2,%3};"
        : "+f"(c[0]), "+f"(c[1]), "+f"(c[2]), "+f"(c[3])
        : "r"(a0), "r"(a1), "r"(a2), "r"(a3), "r"(b0), "r"(b1));
}

__device__ __forceinline__ void cp16(float* smem, const float* gmem) {
    unsigned s = (unsigned)__cvta_generic_to_shared(smem);
    asm volatile("cp.async.cg.shared.global [%0], [%1], 16;\n" :: "r"(s), "l"(gmem));
}
__device__ __forceinline__ void cp_commit() {
    asm volatile("cp.async.commit_group;\n");
}
template <int N>
__device__ __forceinline__ void cp_wait() {
    asm volatile("cp.async.wait_group %0;\n" :: "n"(N));
}

// ---------------- CSR build ----------------
__global__ void hist_kernel(const int* __restrict__ dst) {
    int e = blockIdx.x * blockDim.x + threadIdx.x;
    if (e < N_EDGES) atomicAdd(&g_deg[dst[e]], 1);
}

__global__ void scan_kernel() {
    __shared__ int partial[1024];
    const int t = threadIdx.x;
    const int CH = (N_NODES + 1023) / 1024;   // 49
    int beg = t * CH;
    int sum = 0;
    for (int i = 0; i < CH; i++) {
        int idx = beg + i;
        if (idx < N_NODES) sum += g_deg[idx];
    }
    partial[t] = sum;
    __syncthreads();
    if (t == 0) {
        int run = 0;
        for (int i = 0; i < 1024; i++) { int v = partial[i]; partial[i] = run; run += v; }
    }
    __syncthreads();
    int run = partial[t];
    for (int i = 0; i < CH; i++) {
        int idx = beg + i;
        if (idx < N_NODES) {
            g_ptr[idx]  = run;
            g_fill[idx] = run;
            int d = g_deg[idx];
            g_dinv[idx] = (d > 0) ? rsqrtf((float)d) : 0.0f;
            run += d;
        }
    }
    if (t == 0) g_ptr[N_NODES] = N_EDGES;
}

__global__ void scatter_kernel(const int* __restrict__ src, const int* __restrict__ dst) {
    int e = blockIdx.x * blockDim.x + threadIdx.x;
    if (e < N_EDGES) {
        int d = dst[e];
        int p = atomicAdd(&g_fill[d], 1);
        g_csr_src[p] = src[e];
        g_csr_dst[p] = d;
    }
}

// ---------------- pre-round w1 to tf32 (removes B-side cvt from GEMM1 hot loop) ----------------
__global__ void round_w1_kernel(const float* __restrict__ w) {
    int i = blockIdx.x * blockDim.x + threadIdx.x;
    if (i < HIDDEN * IN_DIM) g_w1r[i] = __uint_as_float(tf32u(w[i]));
}

// ---------------- GEMM1 (tf32, 3-stage cp.async, single barrier/iter, fused layer-0 alar) ----------------
// h = relu(x @ w1^T + b1): [50000,512] x [128,512]^T -> [50000,128]
// BM=128, BN=128, BK=16, 3 stages, 256 threads = 8 warps (2 M x 4 N), warp tile 64x32
#define G1_BK  16
#define G1_PAD 20
#define G1_STG 3
#define G1_SMEM (G1_STG * 2 * 128 * G1_PAD * 4)
__global__ __launch_bounds__(256) void gemm1_tf32_kernel(
    const float* __restrict__ x,
    const float* __restrict__ bias, float* __restrict__ out,
    const float* __restrict__ attl, const float* __restrict__ attr)
{
    extern __shared__ float sm[];
    float (*As)[128][G1_PAD] = (float(*)[128][G1_PAD])sm;
    float (*Bs)[128][G1_PAD] = (float(*)[128][G1_PAD])(sm + G1_STG * 128 * G1_PAD);
    const int bm   = blockIdx.x * 128;
    const int tid  = threadIdx.x;
    const int wid  = tid >> 5;
    const int lane = tid & 31;
    const int wm   = wid & 1;          // 0..1 (64 rows each)
    const int wn   = wid >> 1;         // 0..3 (32 cols each)
    const int g    = lane >> 2;        // 0..7
    const int t    = lane & 3;         // 0..3

    const int lr0 = tid >> 2;          // 0..63
    const int lc  = (tid & 3) * 4;     // 0,4,8,12

    float acc[4][4][4];
    #pragma unroll
    for (int i = 0; i < 4; i++)
        #pragma unroll
        for (int j = 0; j < 4; j++)
            #pragma unroll
            for (int k = 0; k < 4; k++) acc[i][j][k] = 0.0f;

    const int NKB = IN_DIM / G1_BK;    // 32

    // prologue: stages 0, 1
    #pragma unroll
    for (int s = 0; s < G1_STG - 1; s++) {
        const int kb = s * G1_BK;
        #pragma unroll
        for (int i = 0; i < 2; i++) {
            int row = lr0 + 64 * i;
            int gm = bm + row;
            int gms = (gm < N_NODES) ? gm : (N_NODES - 1);
            cp16(&As[s][row][lc], x + (size_t)gms * IN_DIM + kb + lc);
            cp16(&Bs[s][row][lc], g_w1r + (size_t)row * IN_DIM + kb + lc);
        }
        cp_commit();
    }

    int slot = 0;
    for (int kbi = 0; kbi < NKB; kbi++) {
        if (kbi + 1 < NKB) cp_wait<1>(); else cp_wait<0>();
        __syncthreads();

        // prefetch stage kbi+2 into the slot freed two iterations ago (not being read)
        if (kbi + 2 < NKB) {
            int ns = slot + 2; if (ns >= G1_STG) ns -= G1_STG;
            const int kb = (kbi + 2) * G1_BK;
            #pragma unroll
            for (int i = 0; i < 2; i++) {
                int row = lr0 + 64 * i;
                int gm = bm + row;
                int gms = (gm < N_NODES) ? gm : (N_NODES - 1);
                cp16(&As[ns][row][lc], x + (size_t)gms * IN_DIM + kb + lc);
                cp16(&Bs[ns][row][lc], g_w1r + (size_t)row * IN_DIM + kb + lc);
            }
            cp_commit();
        }

        #pragma unroll
        for (int ks = 0; ks < 2; ks++) {
            const int k8 = ks * 8;
            unsigned a[4][4];
            #pragma unroll
            for (int mt = 0; mt < 4; mt++) {
                int rb = wm * 64 + mt * 16;
                a[mt][0] = tf32u(As[slot][rb + g    ][k8 + t    ]);
                a[mt][1] = tf32u(As[slot][rb + g + 8][k8 + t    ]);
                a[mt][2] = tf32u(As[slot][rb + g    ][k8 + t + 4]);
                a[mt][3] = tf32u(As[slot][rb + g + 8][k8 + t + 4]);
            }
            unsigned b[4][2];
            #pragma unroll
            for (int nt = 0; nt < 4; nt++) {
                int nb = wn * 32 + nt * 8;
                b[nt][0] = __float_as_uint(Bs[slot][nb + g][k8 + t    ]);
                b[nt][1] = __float_as_uint(Bs[slot][nb + g][k8 + t + 4]);
            }
            #pragma unroll
            for (int mt = 0; mt < 4; mt++)
                #pragma unroll
                for (int nt = 0; nt < 4; nt++)
                    mma_tf32(acc[mt][nt], a[mt][0], a[mt][1], a[mt][2], a[mt][3],
                             b[nt][0], b[nt][1]);
        }
        slot++; if (slot >= G1_STG) slot = 0;
    }

    // epilogue: bias + relu store, with fused alar (layer 0) partial dots
    float psl[4][2], psr[4][2];
    #pragma unroll
    for (int mt = 0; mt < 4; mt++) { psl[mt][0] = psl[mt][1] = 0.f; psr[mt][0] = psr[mt][1] = 0.f; }

    #pragma unroll
    for (int mt = 0; mt < 4; mt++) {
        int r0 = bm + wm * 64 + mt * 16 + g;
        int r1 = r0 + 8;
        #pragma unroll
        for (int nt = 0; nt < 4; nt++) {
            int c = wn * 32 + nt * 8 + t * 2;
            float b0 = bias[c], b1 = bias[c + 1];
            float la0 = attl[c], la1 = attl[c + 1];
            float ra0 = attr[c], ra1 = attr[c + 1];
            float v00 = fmaxf(acc[mt][nt][0] + b0, 0.0f);
            float v01 = fmaxf(acc[mt][nt][1] + b1, 0.0f);
            float v10 = fmaxf(acc[mt][nt][2] + b0, 0.0f);
            float v11 = fmaxf(acc[mt][nt][3] + b1, 0.0f);
            if (r0 < N_NODES) {
                out[(size_t)r0 * HIDDEN + c    ] = v00;
                out[(size_t)r0 * HIDDEN + c + 1] = v01;
            }
            if (r1 < N_NODES) {
                out[(size_t)r1 * HIDDEN + c    ] = v10;
                out[(size_t)r1 * HIDDEN + c + 1] = v11;
            }
            psl[mt][0] += v00 * la0 + v01 * la1;
            psr[mt][0] += v00 * ra0 + v01 * ra1;
            psl[mt][1] += v10 * la0 + v11 * la1;
            psr[mt][1] += v10 * ra0 + v11 * ra1;
        }
    }

    // all warps have finished MMAs on their own accs; barrier before reusing smem for reduction
    __syncthreads();

    float* red = sm;   // need 1024 floats
    #pragma unroll
    for (int mt = 0; mt < 4; mt++) {
        #pragma unroll
        for (int half = 0; half < 2; half++) {
            float sl = psl[mt][half], sr = psr[mt][half];
            sl += __shfl_xor_sync(0xffffffffu, sl, 1);
            sl += __shfl_xor_sync(0xffffffffu, sl, 2);
            sr += __shfl_xor_sync(0xffffffffu, sr, 1);
            sr += __shfl_xor_sync(0xffffffffu, sr, 2);
            if (t == 0) {
                int rl = wm * 64 + mt * 16 + g + 8 * half;
                red[rl * 4 + wn]       = sl;
                red[512 + rl * 4 + wn] = sr;
            }
        }
    }
    __syncthreads();
    if (tid < 128) {
        int gr = bm + tid;
        if (gr < N_NODES) {
            float a = red[tid * 4] + red[tid * 4 + 1] + red[tid * 4 + 2] + red[tid * 4 + 3];
            float b = red[512 + tid * 4] + red[512 + tid * 4 + 1] +
                      red[512 + tid * 4 + 2] + red[512 + tid * 4 + 3];
            g_al[gr] = a;
            g_ar[gr] = b;
        }
    }
}

// ---------------- GEMM2 (tf32) + fused log_softmax ----------------
// emb = h @ w2^T + b2: [50000,128] x [64,128]^T -> [50000,64]; out = log_softmax(emb)
__global__ __launch_bounds__(256) void gemm2_fused_kernel(
    const float* __restrict__ h, const float* __restrict__ w2,
    const float* __restrict__ b2, float* __restrict__ emb,
    float* __restrict__ outp)
{
    __shared__ float S[2 * 64 * 36];
    float (*As)[36] = (float(*)[36])S;
    float (*Bs)[36] = (float(*)[36])(S + 64 * 36);
    const int bm   = blockIdx.x * 64;
    const int tid  = threadIdx.x;
    const int wid  = tid >> 5;
    const int lane = tid & 31;
    const int wm   = wid & 1;
    const int wn   = wid >> 1;         // 0..3, warpN = 16
    const int g    = lane >> 2;
    const int t    = lane & 3;

    float acc[2][2][4];
    #pragma unroll
    for (int i = 0; i < 2; i++)
        #pragma unroll
        for (int j = 0; j < 2; j++)
            #pragma unroll
            for (int k = 0; k < 4; k++) acc[i][j][k] = 0.0f;

    for (int kb = 0; kb < HIDDEN; kb += 32) {
        #pragma unroll
        for (int i = 0; i < 2; i++) {
            int idx = tid + 256 * i;
            int row = idx >> 3;
            int c4  = (idx & 7) * 4;
            int gm  = bm + row;
            float4 v = make_float4(0.f, 0.f, 0.f, 0.f);
            if (gm < N_NODES)
                v = *(const float4*)(h + (size_t)gm * HIDDEN + kb + c4);
            As[row][c4 + 0] = v.x; As[row][c4 + 1] = v.y;
            As[row][c4 + 2] = v.z; As[row][c4 + 3] = v.w;
        }
        #pragma unroll
        for (int i = 0; i < 2; i++) {
            int idx = tid + 256 * i;
            int row = idx >> 3;
            int c4  = (idx & 7) * 4;
            float4 u = *(const float4*)(w2 + (size_t)row * HIDDEN + kb + c4);
            Bs[row][c4 + 0] = u.x; Bs[row][c4 + 1] = u.y;
            Bs[row][c4 + 2] = u.z; Bs[row][c4 + 3] = u.w;
        }
        __syncthreads();

        #pragma unroll
        for (int ks = 0; ks < 4; ks++) {
            const int k8 = ks * 8;
            unsigned a[2][4];
            #pragma unroll
            for (int mt = 0; mt < 2; mt++) {
                int rb = wm * 32 + mt * 16;
                a[mt][0] = tf32u(As[rb + g    ][k8 + t    ]);
                a[mt][1] = tf32u(As[rb + g + 8][k8 + t    ]);
                a[mt][2] = tf32u(As[rb + g    ][k8 + t + 4]);
                a[mt][3] = tf32u(As[rb + g + 8][k8 + t + 4]);
            }
            unsigned b[2][2];
            #pragma unroll
            for (int nt = 0; nt < 2; nt++) {
                int nb = wn * 16 + nt * 8;
                b[nt][0] = tf32u(Bs[nb + g][k8 + t    ]);
                b[nt][1] = tf32u(Bs[nb + g][k8 + t + 4]);
            }
            #pragma unroll
            for (int mt = 0; mt < 2; mt++)
                #pragma unroll
                for (int nt = 0; nt < 2; nt++)
                    mma_tf32(acc[mt][nt], a[mt][0], a[mt][1], a[mt][2], a[mt][3],
                             b[nt][0], b[nt][1]);
        }
        __syncthreads();
    }

    // stage emb tile in smem (reuse As/Bs region), store emb to gmem
    float (*E)[68] = (float(*)[68])S;   // 64*68 = 4352 <= 4608 floats
    #pragma unroll
    for (int mt = 0; mt < 2; mt++) {
        int rl0 = wm * 32 + mt * 16 + g;
        int rl1 = rl0 + 8;
        int r0 = bm + rl0, r1 = bm + rl1;
        #pragma unroll
        for (int nt = 0; nt < 2; nt++) {
            int c = wn * 16 + nt * 8 + t * 2;
            float b0 = b2[c], b1 = b2[c + 1];
            float v00 = acc[mt][nt][0] + b0, v01 = acc[mt][nt][1] + b1;
            float v10 = acc[mt][nt][2] + b0, v11 = acc[mt][nt][3] + b1;
            E[rl0][c] = v00; E[rl0][c + 1] = v01;
            E[rl1][c] = v10; E[rl1][c + 1] = v11;
            if (r0 < N_NODES) {
                emb[(size_t)r0 * OUT_DIM + c    ] = v00;
                emb[(size_t)r0 * OUT_DIM + c + 1] = v01;
            }
            if (r1 < N_NODES) {
                emb[(size_t)r1 * OUT_DIM + c    ] = v10;
                emb[(size_t)r1 * OUT_DIM + c + 1] = v11;
            }
        }
    }
    __syncthreads();

    // warp-per-row log_softmax: 8 warps x 8 rows
    #pragma unroll
    for (int i = 0; i < 8; i++) {
        int rl = wid * 8 + i;
        int gm = bm + rl;
        float e0 = E[rl][lane];
        float e1 = E[rl][lane + 32];
        float m = fmaxf(e0, e1);
        #pragma unroll
        for (int o = 16; o; o >>= 1) m = fmaxf(m, __shfl_xor_sync(0xffffffffu, m, o));
        float s = expf(e0 - m) + expf(e1 - m);
        #pragma unroll
        for (int o = 16; o; o >>= 1) s += __shfl_xor_sync(0xffffffffu, s, o);
        float lse = m + logf(s);
        if (gm < N_NODES) {
            outp[(size_t)gm * OUT_DIM + lane]      = e0 - lse;
            outp[(size_t)gm * OUT_DIM + 32 + lane] = e1 - lse;
        }
    }
}

// ---------------- per-layer: edge weights packed {src, w} ----------------
__global__ void weight_kernel() {
    int j = blockIdx.x * blockDim.x + threadIdx.x;
    if (j >= N_EDGES) return;
    int s = g_csr_src[j];
    int d = g_csr_dst[j];
    float wv = tanhf(g_al[s] + g_ar[d]) * (g_dinv[s] * g_dinv[d]);
    g_ew[j] = make_int2(s, __float_as_int(wv));
}

// ---------------- per-layer: aggregation (warp/node, CSR, unroll-4, fused next-layer alar) ----------------
__global__ void agg_kernel(const float* __restrict__ hcur,
                           const float* __restrict__ raw,
                           float* __restrict__ hnext,
                           const float* __restrict__ attl,   // next layer (null = skip)
                           const float* __restrict__ attr)
{
    int node = (blockIdx.x * blockDim.x + threadIdx.x) >> 5;
    int lane = threadIdx.x & 31;
    if (node >= N_NODES) return;

    const int beg = g_ptr[node];
    const int end = g_ptr[node + 1];

    float4 rv = *((const float4*)(raw + (size_t)node * HIDDEN) + lane);
    float4 acc = make_float4(EPS * rv.x, EPS * rv.y, EPS * rv.z, EPS * rv.w);

    int j = beg;
    for (; j + 4 <= end; j += 4) {
        int2 e0 = __ldg(&g_ew[j + 0]);
        int2 e1 = __ldg(&g_ew[j + 1]);
        int2 e2 = __ldg(&g_ew[j + 2]);
        int2 e3 = __ldg(&g_ew[j + 3]);
        float w0 = __int_as_float(e0.y);
        float w1 = __int_as_float(e1.y);
        float w2 = __int_as_float(e2.y);
        float w3 = __int_as_float(e3.y);
        float4 v0 = __ldg((const float4*)(hcur + (size_t)e0.x * HIDDEN) + lane);
        float4 v1 = __ldg((const float4*)(hcur + (size_t)e1.x * HIDDEN) + lane);
        float4 v2 = __ldg((const float4*)(hcur + (size_t)e2.x * HIDDEN) + lane);
        float4 v3 = __ldg((const float4*)(hcur + (size_t)e3.x * HIDDEN) + lane);
        acc.x = fmaf(w0, v0.x, acc.x); acc.y = fmaf(w0, v0.y, acc.y);
        acc.z = fmaf(w0, v0.z, acc.z); acc.w = fmaf(w0, v0.w, acc.w);
        acc.x = fmaf(w1, v1.x, acc.x); acc.y = fmaf(w1, v1.y, acc.y);
        acc.z = fmaf(w1, v1.z, acc.z); acc.w = fmaf(w1, v1.w, acc.w);
        acc.x = fmaf(w2, v2.x, acc.x); acc.y = fmaf(w2, v2.y, acc.y);
        acc.z = fmaf(w2, v2.z, acc.z); acc.w = fmaf(w2, v2.w, acc.w);
        acc.x = fmaf(w3, v3.x, acc.x); acc.y = fmaf(w3, v3.y, acc.y);
        acc.z = fmaf(w3, v3.z, acc.z); acc.w = fmaf(w3, v3.w, acc.w);
    }
    for (; j < end; j++) {
        int2 e = __ldg(&g_ew[j]);
        float wgt = __int_as_float(e.y);
        float4 hs = __ldg((const float4*)(hcur + (size_t)e.x * HIDDEN) + lane);
        acc.x = fmaf(wgt, hs.x, acc.x);
        acc.y = fmaf(wgt, hs.y, acc.y);
        acc.z = fmaf(wgt, hs.z, acc.z);
        acc.w = fmaf(wgt, hs.w, acc.w);
    }
    *((float4*)(hnext + (size_t)node * HIDDEN) + lane) = acc;

    if (attl != nullptr) {
        float4 lv = ((const float4*)attl)[lane];
        float4 rv2 = ((const float4*)attr)[lane];
        float sl = acc.x * lv.x + acc.y * lv.y + acc.z * lv.z + acc.w * lv.w;
        float sr = acc.x * rv2.x + acc.y * rv2.y + acc.z * rv2.z + acc.w * rv2.w;
        #pragma unroll
        for (int o = 16; o; o >>= 1) {
            sl += __shfl_xor_sync(0xffffffffu, sl, o);
            sr += __shfl_xor_sync(0xffffffffu, sr, o);
        }
        if (lane == 0) { g_al[node] = sl; g_ar[node] = sr; }
    }
}

// ---------------- launch (single stream, fully capture-safe) ----------------
extern "C" void kernel_launch(void* const* d_in, const int* in_sizes, int n_in,
                              void* d_out, int out_size)
{
    const float* x     = (const float*)d_in[0];
    const int*   ei    = (const int*)  d_in[1];
    const float* t1_w  = (const float*)d_in[2];
    const float* t1_b  = (const float*)d_in[3];
    const float* t2_w  = (const float*)d_in[4];
    const float* t2_b  = (const float*)d_in[5];
    const float* att_l = (const float*)d_in[6];
    const float* att_r = (const float*)d_in[7];
    (void)in_sizes; (void)n_in; (void)out_size;

    const int* src = ei;
    const int* dst = ei + N_EDGES;

    float *h0, *hA, *hB;
    int* degp;
    cudaGetSymbolAddress((void**)&h0, g_h0);
    cudaGetSymbolAddress((void**)&hA, g_hA);
    cudaGetSymbolAddress((void**)&hB, g_hB);
    cudaGetSymbolAddress((void**)&degp, g_deg);

    float* outp = (float*)d_out;                              // [50000, 64] log_softmax
    float* emb  = (float*)d_out + (size_t)N_NODES * OUT_DIM;  // [50000, 64] emb

    // opt-in to 60KB dynamic smem (idempotent; immediate API, not a stream op)
    cudaFuncSetAttribute(gemm1_tf32_kernel,
                         cudaFuncAttributeMaxDynamicSharedMemorySize, G1_SMEM);

    // CSR build
    cudaMemsetAsync(degp, 0, N_NODES * sizeof(int));
    hist_kernel<<<(N_EDGES + 255) / 256, 256>>>(dst);
    scan_kernel<<<1, 1024>>>();
    scatter_kernel<<<(N_EDGES + 255) / 256, 256>>>(src, dst);

    // pre-round w1, then GEMM1 (+relu, +fused layer-0 alar)
    round_w1_kernel<<<(HIDDEN * IN_DIM + 255) / 256, 256>>>(t1_w);
    gemm1_tf32_kernel<<<(N_NODES + 127) / 128, 256, G1_SMEM>>>(
        x, t1_b, h0, att_l + 0 * HIDDEN, att_r + 0 * HIDDEN);

    const int warp_blocks = (N_NODES * 32 + 255) / 256;
    const int edge_blocks = (N_EDGES + 255) / 256;

    weight_kernel<<<edge_blocks, 256>>>();
    agg_kernel<<<warp_blocks, 256>>>(h0, h0, hA, att_l + 1 * HIDDEN, att_r + 1 * HIDDEN);

    weight_kernel<<<edge_blocks, 256>>>();
    agg_kernel<<<warp_blocks, 256>>>(hA, h0, hB, att_l + 2 * HIDDEN, att_r + 2 * HIDDEN);

    weight_kernel<<<edge_blocks, 256>>>();
    agg_kernel<<<warp_blocks, 256>>>(hB, h0, hA, nullptr, nullptr);

    // GEMM2 + fused log_softmax
    gemm2_fused_kernel<<<(N_NODES + 63) / 64, 256>>>(hA, t2_w, t2_b, emb, outp);
}